// round 2
// baseline (speedup 1.0000x reference)
#include <cuda_runtime.h>

// YOLOv1 loss: [B,7,7,30] x2 f32 -> scalar. HBM-bound (~193 MB read).
// R2: 2 kernels (main + finalize), no zero kernel, no atomics.
// Main: coalesced float4 loads, compile-time unrolled for high MLP,
// padded smem scatter (stride 31), thread-per-cell compute, block partial
// into __device__ array. Finalize: deterministic double-sum of partials.

#define TPB    128
#define CPB    128   // cells per block (== TPB)
#define DIM    30
#define PADDIM 31
#define NV4    ((CPB * DIM) / 4)   // 960 float4 per tensor per block
#define EPSF   1e-6f
#define MAX_BLOCKS 16384

__device__ float g_part[MAX_BLOCKS];

__device__ __forceinline__ float sq(float x) { return x * x; }

__device__ __forceinline__ float iou_yolo(const float* __restrict__ a,
                                          const float* __restrict__ b) {
    float ax1 = a[0] - 0.5f * a[2], ax2 = a[0] + 0.5f * a[2];
    float ay1 = a[1] - 0.5f * a[3], ay2 = a[1] + 0.5f * a[3];
    float bx1 = b[0] - 0.5f * b[2], bx2 = b[0] + 0.5f * b[2];
    float by1 = b[1] - 0.5f * b[3], by2 = b[1] + 0.5f * b[3];
    float iw = fmaxf(fminf(ax2, bx2) - fmaxf(ax1, bx1), 0.0f);
    float ih = fmaxf(fminf(ay2, by2) - fmaxf(ay1, by1), 0.0f);
    float inter = iw * ih;
    float a1 = fabsf((ax2 - ax1) * (ay2 - ay1));
    float a2 = fabsf((bx2 - bx1) * (by2 - by1));
    return inter / (a1 + a2 - inter + EPSF);
}

__global__ void __launch_bounds__(TPB)
yolo_loss_kernel(const float* __restrict__ yt_g,
                 const float* __restrict__ yp_g,
                 long long n_cells) {
    __shared__ float st[CPB * PADDIM];
    __shared__ float sp[CPB * PADDIM];

    long long base = (long long)blockIdx.x * CPB;
    const int tid = threadIdx.x;

    const float4* yt4 = (const float4*)(yt_g + base * DIM);
    const float4* yp4 = (const float4*)(yp_g + base * DIM);

    bool full = (base + CPB <= n_cells);

    if (full) {
        // Full block: 960 float4 per tensor, 8 fixed iterations (last one
        // half-predicated). Front-batch ALL loads first for max MLP, then
        // scatter into smem.
        float4 tv[8], pv[8];
#pragma unroll
        for (int k = 0; k < 8; k++) {
            int j = k * TPB + tid;
            if (j < NV4) { tv[k] = yt4[j]; pv[k] = yp4[j]; }
        }
#pragma unroll
        for (int k = 0; k < 8; k++) {
            int j = k * TPB + tid;
            if (j < NV4) {
                int f = 4 * j;
                float t[4] = {tv[k].x, tv[k].y, tv[k].z, tv[k].w};
                float p[4] = {pv[k].x, pv[k].y, pv[k].z, pv[k].w};
#pragma unroll
                for (int q = 0; q < 4; q++) {
                    int idx = f + q;
                    int c = idx / DIM;
                    int e = idx - c * DIM;
                    st[c * PADDIM + e] = t[q];
                    sp[c * PADDIM + e] = p[q];
                }
            }
        }
    } else {
        int cells = (int)(n_cells - base);
        int nflt = cells * DIM;
        const float* yt = (const float*)yt4;
        const float* yp = (const float*)yp4;
        for (int j = tid; j < nflt; j += TPB) {
            int c = j / DIM;
            int e = j - c * DIM;
            st[c * PADDIM + e] = yt[j];
            sp[c * PADDIM + e] = yp[j];
        }
    }
    __syncthreads();

    float per = 0.0f;
    if (base + tid < n_cells) {
        const float* t = st + tid * PADDIM;
        const float* p = sp + tid * PADDIM;

        float obj = (t[4] == 1.0f) ? 1.0f : 0.0f;

        float iou1 = iou_yolo(t, p);
        float iou2 = iou_yolo(t, p + 5);
        bool best1 = iou1 > iou2;

        const float* bh = best1 ? p : (p + 5);
        float conf_hat  = best1 ? p[4] : p[9];
        float other_hat = best1 ? p[9] : p[4];

        float xy = sq(t[0] - bh[0]) + sq(t[1] - bh[1]);
        float wh = sq(sqrtf(t[2]) - sqrtf(fabsf(bh[2] + EPSF)))
                 + sq(sqrtf(t[3]) - sqrtf(fabsf(bh[3] + EPSF)));
        float obj_conf     = sq(t[4] - conf_hat);
        float noobj_in_obj = 0.5f * other_hat * other_hat;
        float noobj_cells  = 0.5f * (sq(t[4] - p[4]) + sq(t[4] - p[9]));

        float cls = 0.0f;
#pragma unroll
        for (int k = 0; k < 20; k++) cls += sq(t[10 + k] - p[10 + k]);

        per = obj * (5.0f * (xy + wh) + obj_conf + noobj_in_obj + cls)
            + (1.0f - obj) * noobj_cells;
    }

    // Warp reduce, then block reduce.
#pragma unroll
    for (int o = 16; o > 0; o >>= 1)
        per += __shfl_xor_sync(0xFFFFFFFFu, per, o);

    __shared__ float wsum[TPB / 32];
    int lane = tid & 31;
    int warp = tid >> 5;
    if (lane == 0) wsum[warp] = per;
    __syncthreads();

    if (tid == 0) {
        float s = 0.0f;
#pragma unroll
        for (int i = 0; i < TPB / 32; i++) s += wsum[i];
        g_part[blockIdx.x] = s;   // non-atomic, deterministic
    }
}

#define FTPB 256

__global__ void __launch_bounds__(FTPB)
finalize_kernel(float* __restrict__ out, int nblocks, double inv_batch) {
    int tid = threadIdx.x;
    double s = 0.0;
    for (int i = tid; i < nblocks; i += FTPB)
        s += (double)g_part[i];

    // warp reduce in double
#pragma unroll
    for (int o = 16; o > 0; o >>= 1)
        s += __shfl_xor_sync(0xFFFFFFFFu, s, o);

    __shared__ double wsum[FTPB / 32];
    int lane = tid & 31;
    int warp = tid >> 5;
    if (lane == 0) wsum[warp] = s;
    __syncthreads();

    if (tid == 0) {
        double tot = 0.0;
#pragma unroll
        for (int i = 0; i < FTPB / 32; i++) tot += wsum[i];
        out[0] = (float)(tot * inv_batch);
    }
}

extern "C" void kernel_launch(void* const* d_in, const int* in_sizes, int n_in,
                              void* d_out, int out_size) {
    const float* yt = (const float*)d_in[0];   // y_trues
    const float* yp = (const float*)d_in[1];   // y_preds
    long long n_cells = (long long)in_sizes[0] / DIM;   // batch * 49
    long long batch   = n_cells / 49;
    int blocks = (int)((n_cells + CPB - 1) / CPB);
    if (blocks > MAX_BLOCKS) blocks = MAX_BLOCKS;  // safety (not hit at bench size)

    yolo_loss_kernel<<<blocks, TPB>>>(yt, yp, n_cells);
    finalize_kernel<<<1, FTPB>>>((float*)d_out, blocks, 1.0 / (double)batch);
}

// round 3
// speedup vs baseline: 1.2478x; 1.2478x over previous
#include <cuda_runtime.h>
#include <cstdint>

// YOLOv1 loss: [B,7,7,30] x2 f32 -> scalar. HBM-bound (~193 MB read).
// R3: ONE kernel. cp.async (LDGSTS) global->smem, unpadded stride-30 layout
// (2-way LDS conflicts only), thread-per-cell compute, block partial ->
// g_part, last-arriving block reduces partials in double and writes d_out.

#define TPB    128
#define CPB    128             // cells per block
#define DIM    30
#define NV4    ((CPB * DIM) / 4)   // 960 float4 per tensor per full block
#define EPSF   1e-6f
#define MAX_BLOCKS 16384

__device__ float g_part[MAX_BLOCKS];
__device__ unsigned int g_count = 0;

__device__ __forceinline__ float sq(float x) { return x * x; }

__device__ __forceinline__ void cp16(uint32_t smem_dst, const void* gsrc) {
    asm volatile("cp.async.cg.shared.global [%0], [%1], 16;\n"
                 :: "r"(smem_dst), "l"(gsrc));
}

__device__ __forceinline__ float iou_yolo(const float* __restrict__ a,
                                          const float* __restrict__ b) {
    float ax1 = a[0] - 0.5f * a[2], ax2 = a[0] + 0.5f * a[2];
    float ay1 = a[1] - 0.5f * a[3], ay2 = a[1] + 0.5f * a[3];
    float bx1 = b[0] - 0.5f * b[2], bx2 = b[0] + 0.5f * b[2];
    float by1 = b[1] - 0.5f * b[3], by2 = b[1] + 0.5f * b[3];
    float iw = fmaxf(fminf(ax2, bx2) - fmaxf(ax1, bx1), 0.0f);
    float ih = fmaxf(fminf(ay2, by2) - fmaxf(ay1, by1), 0.0f);
    float inter = iw * ih;
    float a1 = fabsf((ax2 - ax1) * (ay2 - ay1));
    float a2 = fabsf((bx2 - bx1) * (by2 - by1));
    return inter / (a1 + a2 - inter + EPSF);
}

__global__ void __launch_bounds__(TPB)
yolo_loss_kernel(const float* __restrict__ yt_g,
                 const float* __restrict__ yp_g,
                 long long n_cells,
                 float* __restrict__ out,
                 double inv_batch) {
    __shared__ float st[CPB * DIM];   // 15360 B
    __shared__ float sp[CPB * DIM];   // 15360 B
    __shared__ float wsum[TPB / 32];
    __shared__ int   s_last;

    const int tid = threadIdx.x;
    long long base = (long long)blockIdx.x * CPB;
    const float* yt = yt_g + base * DIM;
    const float* yp = yp_g + base * DIM;

    bool full = (base + CPB <= n_cells);

    if (full) {
        // cp.async: 960 x 16B per tensor, all in flight before the wait.
        uint32_t st_b = (uint32_t)__cvta_generic_to_shared(st);
        uint32_t sp_b = (uint32_t)__cvta_generic_to_shared(sp);
        const float4* yt4 = (const float4*)yt;
        const float4* yp4 = (const float4*)yp;
#pragma unroll
        for (int k = 0; k < 8; k++) {
            int j = k * TPB + tid;
            if (j < NV4) {
                cp16(st_b + j * 16, yt4 + j);
                cp16(sp_b + j * 16, yp4 + j);
            }
        }
        asm volatile("cp.async.commit_group;\n" ::: "memory");
        asm volatile("cp.async.wait_group 0;\n" ::: "memory");
    } else {
        int nflt = (int)(n_cells - base) * DIM;
        for (int j = tid; j < nflt; j += TPB) {
            st[j] = yt[j];
            sp[j] = yp[j];
        }
    }
    __syncthreads();

    float per = 0.0f;
    if (base + tid < n_cells) {
        const float* t = st + tid * DIM;
        const float* p = sp + tid * DIM;

        float obj = (t[4] == 1.0f) ? 1.0f : 0.0f;

        float iou1 = iou_yolo(t, p);
        float iou2 = iou_yolo(t, p + 5);
        bool best1 = iou1 > iou2;

        const float* bh = best1 ? p : (p + 5);
        float conf_hat  = best1 ? p[4] : p[9];
        float other_hat = best1 ? p[9] : p[4];

        float xy = sq(t[0] - bh[0]) + sq(t[1] - bh[1]);
        float wh = sq(sqrtf(t[2]) - sqrtf(fabsf(bh[2] + EPSF)))
                 + sq(sqrtf(t[3]) - sqrtf(fabsf(bh[3] + EPSF)));
        float obj_conf     = sq(t[4] - conf_hat);
        float noobj_in_obj = 0.5f * other_hat * other_hat;
        float noobj_cells  = 0.5f * (sq(t[4] - p[4]) + sq(t[4] - p[9]));

        float cls = 0.0f;
#pragma unroll
        for (int k = 0; k < 20; k++) cls += sq(t[10 + k] - p[10 + k]);

        per = obj * (5.0f * (xy + wh) + obj_conf + noobj_in_obj + cls)
            + (1.0f - obj) * noobj_cells;
    }

    // Warp then block reduce (float; per-block partial is small).
#pragma unroll
    for (int o = 16; o > 0; o >>= 1)
        per += __shfl_xor_sync(0xFFFFFFFFu, per, o);

    int lane = tid & 31;
    int warp = tid >> 5;
    if (lane == 0) wsum[warp] = per;
    __syncthreads();

    if (tid == 0) {
        float s = 0.0f;
#pragma unroll
        for (int i = 0; i < TPB / 32; i++) s += wsum[i];
        g_part[blockIdx.x] = s;
        __threadfence();
        unsigned int prev = atomicAdd(&g_count, 1u);
        s_last = (prev == gridDim.x - 1) ? 1 : 0;
    }
    __syncthreads();

    if (s_last) {
        // Last block: deterministic double-precision sum of all partials.
        int nb = gridDim.x;
        const volatile float* vp = g_part;
        double s = 0.0;
        for (int i = tid; i < nb; i += TPB)
            s += (double)vp[i];

#pragma unroll
        for (int o = 16; o > 0; o >>= 1)
            s += __shfl_xor_sync(0xFFFFFFFFu, s, o);

        __shared__ double dsum[TPB / 32];
        if (lane == 0) dsum[warp] = s;
        __syncthreads();

        if (tid == 0) {
            double tot = 0.0;
#pragma unroll
            for (int i = 0; i < TPB / 32; i++) tot += dsum[i];
            out[0] = (float)(tot * inv_batch);
            g_count = 0;   // reset for next graph replay
        }
    }
}

extern "C" void kernel_launch(void* const* d_in, const int* in_sizes, int n_in,
                              void* d_out, int out_size) {
    const float* yt = (const float*)d_in[0];   // y_trues
    const float* yp = (const float*)d_in[1];   // y_preds
    long long n_cells = (long long)in_sizes[0] / DIM;   // batch * 49
    long long batch   = n_cells / 49;
    int blocks = (int)((n_cells + CPB - 1) / CPB);
    if (blocks > MAX_BLOCKS) blocks = MAX_BLOCKS;  // not hit at bench size

    yolo_loss_kernel<<<blocks, TPB>>>(yt, yp, n_cells,
                                      (float*)d_out, 1.0 / (double)batch);
}

// round 4
// speedup vs baseline: 1.3299x; 1.0658x over previous
#include <cuda_runtime.h>
#include <cstdint>

// YOLOv1 loss: [B,7,7,30] x2 f32 -> scalar. HBM-bound (~193 MB read).
// R4: persistent blocks + 2-stage cp.async pipeline. While computing tile i,
// tile i+1 streams into the other smem buffer -> continuous load issue per
// block (fixes the 65% DRAM duty cycle of the serial load/compute scheme).
// Tile = 96 cells so 2 stages fit static smem (46 KB < 48 KB limit).
// Per-thread float accumulation across tiles; ONE block reduce at the end;
// last-arriving block sums partials in double and writes d_out.

#define TPB    96
#define CPB    96              // cells per tile (== TPB)
#define DIM    30
#define TILE_FLTS (CPB * DIM)  // 2880 floats per tensor per tile
#define NV4    (TILE_FLTS / 4) // 720 float4
#define EPSF   1e-6f
#define GRID_BLOCKS 608        // ~4 blocks/SM on 148-152 SMs
#define MAX_BLOCKS  4096

__device__ float g_part[MAX_BLOCKS];
__device__ unsigned int g_count = 0;

__device__ __forceinline__ float sq(float x) { return x * x; }

__device__ __forceinline__ void cp16(uint32_t smem_dst, const void* gsrc) {
    asm volatile("cp.async.cg.shared.global [%0], [%1], 16;\n"
                 :: "r"(smem_dst), "l"(gsrc));
}
__device__ __forceinline__ void cp8(uint32_t smem_dst, const void* gsrc) {
    asm volatile("cp.async.ca.shared.global [%0], [%1], 8;\n"
                 :: "r"(smem_dst), "l"(gsrc));
}

__device__ __forceinline__ float iou_yolo(const float* __restrict__ a,
                                          const float* __restrict__ b) {
    float ax1 = a[0] - 0.5f * a[2], ax2 = a[0] + 0.5f * a[2];
    float ay1 = a[1] - 0.5f * a[3], ay2 = a[1] + 0.5f * a[3];
    float bx1 = b[0] - 0.5f * b[2], bx2 = b[0] + 0.5f * b[2];
    float by1 = b[1] - 0.5f * b[3], by2 = b[1] + 0.5f * b[3];
    float iw = fmaxf(fminf(ax2, bx2) - fmaxf(ax1, bx1), 0.0f);
    float ih = fmaxf(fminf(ay2, by2) - fmaxf(ay1, by1), 0.0f);
    float inter = iw * ih;
    float a1 = fabsf((ax2 - ax1) * (ay2 - ay1));
    float a2 = fabsf((bx2 - bx1) * (by2 - by1));
    return inter / (a1 + a2 - inter + EPSF);
}

__global__ void __launch_bounds__(TPB)
yolo_loss_kernel(const float* __restrict__ yt_g,
                 const float* __restrict__ yp_g,
                 long long n_cells,
                 long long n_tiles,
                 float* __restrict__ out,
                 double inv_batch) {
    // Double-buffered tiles: [stage][tensor][TILE_FLTS]
    __shared__ float sbuf[2][2][TILE_FLTS];   // 46080 B
    __shared__ float wsum[TPB / 32];
    __shared__ int   s_last;

    const int tid = threadIdx.x;
    const int nb  = gridDim.x;

    uint32_t sb_base = (uint32_t)__cvta_generic_to_shared(&sbuf[0][0][0]);

    // Issue one tile's loads into stage buffer `buf` (one commit group).
    auto issue = [&](long long tile, int buf) {
        long long base = tile * CPB;
        uint32_t st_b = sb_base + (uint32_t)(buf * 2 * TILE_FLTS) * 4u;
        uint32_t sp_b = st_b + TILE_FLTS * 4u;
        const float4* yt4 = (const float4*)(yt_g + base * DIM);
        const float4* yp4 = (const float4*)(yp_g + base * DIM);
        if (base + CPB <= n_cells) {
#pragma unroll
            for (int k = 0; k < 8; k++) {
                int j = k * TPB + tid;
                if (j < NV4) {
                    cp16(st_b + j * 16, yt4 + j);
                    cp16(sp_b + j * 16, yp4 + j);
                }
            }
        } else {
            int nflt = (int)(n_cells - base) * DIM;
            int nv4 = nflt >> 2;
            for (int j = tid; j < nv4; j += TPB) {
                cp16(st_b + j * 16, yt4 + j);
                cp16(sp_b + j * 16, yp4 + j);
            }
            if ((nflt & 3) && tid == 0) {   // 30*c is even -> remainder is 2 floats
                int f = nv4 * 4;
                cp8(st_b + f * 4, (const float*)yt4 + f);
                cp8(sp_b + f * 4, (const float*)yp4 + f);
            }
        }
        asm volatile("cp.async.commit_group;\n" ::: "memory");
    };

    float acc = 0.0f;
    long long t = blockIdx.x;
    int buf = 0;

    if (t < n_tiles) issue(t, 0);

    for (; t < n_tiles; t += nb) {
        long long nxt = t + nb;
        bool has_next = (nxt < n_tiles);
        if (has_next) issue(nxt, buf ^ 1);

        if (has_next) asm volatile("cp.async.wait_group 1;\n" ::: "memory");
        else          asm volatile("cp.async.wait_group 0;\n" ::: "memory");
        __syncthreads();

        long long base = t * CPB;
        if (base + tid < n_cells) {
            const float* tt = &sbuf[buf][0][tid * DIM];
            const float* pp = &sbuf[buf][1][tid * DIM];

            float obj = (tt[4] == 1.0f) ? 1.0f : 0.0f;

            float iou1 = iou_yolo(tt, pp);
            float iou2 = iou_yolo(tt, pp + 5);
            bool best1 = iou1 > iou2;

            const float* bh = best1 ? pp : (pp + 5);
            float conf_hat  = best1 ? pp[4] : pp[9];
            float other_hat = best1 ? pp[9] : pp[4];

            float xy = sq(tt[0] - bh[0]) + sq(tt[1] - bh[1]);
            float wh = sq(sqrtf(tt[2]) - sqrtf(fabsf(bh[2] + EPSF)))
                     + sq(sqrtf(tt[3]) - sqrtf(fabsf(bh[3] + EPSF)));
            float obj_conf     = sq(tt[4] - conf_hat);
            float noobj_in_obj = 0.5f * other_hat * other_hat;
            float noobj_cells  = 0.5f * (sq(tt[4] - pp[4]) + sq(tt[4] - pp[9]));

            float cls = 0.0f;
#pragma unroll
            for (int k = 0; k < 20; k++) cls += sq(tt[10 + k] - pp[10 + k]);

            acc += obj * (5.0f * (xy + wh) + obj_conf + noobj_in_obj + cls)
                 + (1.0f - obj) * noobj_cells;
        }

        __syncthreads();   // all reads of buf done before it is refilled
        buf ^= 1;
    }

    // One block reduction at the end.
#pragma unroll
    for (int o = 16; o > 0; o >>= 1)
        acc += __shfl_xor_sync(0xFFFFFFFFu, acc, o);

    int lane = tid & 31;
    int warp = tid >> 5;
    if (lane == 0) wsum[warp] = acc;
    __syncthreads();

    if (tid == 0) {
        float s = 0.0f;
#pragma unroll
        for (int i = 0; i < TPB / 32; i++) s += wsum[i];
        g_part[blockIdx.x] = s;
        __threadfence();
        unsigned int prev = atomicAdd(&g_count, 1u);
        s_last = (prev == gridDim.x - 1) ? 1 : 0;
    }
    __syncthreads();

    if (s_last) {
        const volatile float* vp = g_part;
        double s = 0.0;
        for (int i = tid; i < nb; i += TPB)
            s += (double)vp[i];
#pragma unroll
        for (int o = 16; o > 0; o >>= 1)
            s += __shfl_xor_sync(0xFFFFFFFFu, s, o);

        __shared__ double dsum[TPB / 32];
        if (lane == 0) dsum[warp] = s;
        __syncthreads();

        if (tid == 0) {
            double tot = 0.0;
#pragma unroll
            for (int i = 0; i < TPB / 32; i++) tot += dsum[i];
            out[0] = (float)(tot * inv_batch);
            g_count = 0;   // reset for next graph replay
        }
    }
}

extern "C" void kernel_launch(void* const* d_in, const int* in_sizes, int n_in,
                              void* d_out, int out_size) {
    const float* yt = (const float*)d_in[0];   // y_trues
    const float* yp = (const float*)d_in[1];   // y_preds
    long long n_cells = (long long)in_sizes[0] / DIM;     // batch * 49
    long long batch   = n_cells / 49;
    long long n_tiles = (n_cells + CPB - 1) / CPB;

    int blocks = GRID_BLOCKS;
    if ((long long)blocks > n_tiles) blocks = (int)n_tiles;
    if (blocks > MAX_BLOCKS) blocks = MAX_BLOCKS;

    yolo_loss_kernel<<<blocks, TPB>>>(yt, yp, n_cells, n_tiles,
                                      (float*)d_out, 1.0 / (double)batch);
}